// round 2
// baseline (speedup 1.0000x reference)
#include <cuda_runtime.h>
#include <math.h>

#define CO   256
#define HW   128
#define NB   16

// ---------------- device scratch (no allocations allowed) ----------------
__device__ float g_y[(size_t)NB * CO * HW * HW];        // 268 MB intermediate
__device__ float g_bank1[4 * 128 * 9 * CO];             // [k][ci][tap][co]
__device__ float g_bank2[4 * 256 * 9 * CO];
__device__ float g_gap[NB * 256];
__device__ float g_attn[NB * 4];

// ---------------- irfft2 synthesis: 12 reals -> 9 spatial taps ----------------
// jnp.fft.irfft2(Fr + i Fi, s=(3,3)):
//   G[y,kx]  = sum_ky F[ky,kx] * e^{+2*pi*i*ky*y/3}          (ifft along -2, 1/3 folded later)
//   w[y,x]   = (Re G[y,0] + 2*(Re G[y,1]*cos(2pi x/3) - Im G[y,1]*sin(2pi x/3))) / 9
// (c2r drops Im of bin 0.)
__global__ void synth_kernel(const float* __restrict__ fr, const float* __restrict__ fi,
                             float* __restrict__ bank, int Ci) {
    int idx = blockIdx.x * blockDim.x + threadIdx.x;
    int total = 4 * CO * Ci;
    if (idx >= total) return;
    int ci = idx % Ci;
    int t  = idx / Ci;
    int co = t % CO;
    int k  = t / CO;

    const float* pr = fr + (size_t)idx * 6;   // layout [K][Co][Ci][3][2] contiguous
    const float* pi = fi + (size_t)idx * 6;
    float Fr[3][2], Fi[3][2];
#pragma unroll
    for (int a = 0; a < 3; a++)
#pragma unroll
        for (int x2 = 0; x2 < 2; x2++) {
            Fr[a][x2] = pr[a * 2 + x2];
            Fi[a][x2] = pi[a * 2 + x2];
        }

    const float Hs = 0.86602540378443864676f;           // sqrt(3)/2
    const float cm[3] = { 1.f, -0.5f, -0.5f };          // cos(2*pi*m/3)
    const float sm[3] = { 0.f,  Hs,   -Hs  };           // sin(2*pi*m/3)

    float* outp = bank + ((size_t)(k * Ci + ci) * 9) * CO + co;

#pragma unroll
    for (int y = 0; y < 3; y++) {
        float Gr0 = 0.f, Gr1 = 0.f, Gi1 = 0.f;
#pragma unroll
        for (int ky = 0; ky < 3; ky++) {
            int m = (ky * y) % 3;
            float c = cm[m], s = sm[m];
            Gr0 += Fr[ky][0] * c - Fi[ky][0] * s;
            Gr1 += Fr[ky][1] * c - Fi[ky][1] * s;
            Gi1 += Fr[ky][1] * s + Fi[ky][1] * c;
        }
#pragma unroll
        for (int xx = 0; xx < 3; xx++) {
            float w = (Gr0 + 2.f * (Gr1 * cm[xx] - Gi1 * sm[xx])) * (1.f / 9.f);
            outp[(y * 3 + xx) * CO] = w;
        }
    }
}

// ---------------- global average pool: one block per (b, c) ----------------
__global__ void gap_kernel(const float* __restrict__ in, float* __restrict__ gap) {
    const float4* p = reinterpret_cast<const float4*>(in + (size_t)blockIdx.x * (HW * HW));
    float s = 0.f;
    for (int i = threadIdx.x; i < HW * HW / 4; i += 256) {
        float4 v = p[i];
        s += (v.x + v.y) + (v.z + v.w);
    }
    __shared__ float red[8];
    for (int o = 16; o; o >>= 1) s += __shfl_down_sync(0xffffffffu, s, o);
    if ((threadIdx.x & 31) == 0) red[threadIdx.x >> 5] = s;
    __syncthreads();
    if (threadIdx.x < 8) {
        s = red[threadIdx.x];
        for (int o = 4; o; o >>= 1) s += __shfl_down_sync(0xffu, s, o);
        if (threadIdx.x == 0) gap[blockIdx.x] = s * (1.f / (HW * HW));
    }
}

// ---------------- GAP -> MLP -> softmax attention, one block per sample ----------------
__global__ void attn_kernel(const float* __restrict__ gap, const float* __restrict__ w1,
                            const float* __restrict__ b1, const float* __restrict__ w2,
                            const float* __restrict__ b2, float* __restrict__ attn,
                            int C, int Hd) {
    __shared__ float gs[256];
    __shared__ float hbuf[64];
    int b = blockIdx.x;
    for (int i = threadIdx.x; i < C; i += blockDim.x) gs[i] = gap[b * C + i];
    __syncthreads();
    for (int j = threadIdx.x; j < Hd; j += blockDim.x) {
        float s = b1[j];
        for (int c = 0; c < C; c++) s += gs[c] * w1[c * Hd + j];
        hbuf[j] = fmaxf(s, 0.f);
    }
    __syncthreads();
    if (threadIdx.x == 0) {
        float l[4];
        float m = -1e30f;
        for (int k = 0; k < 4; k++) {
            float s = b2[k];
            for (int j = 0; j < Hd; j++) s += hbuf[j] * w2[j * 4 + k];
            l[k] = s;
            m = fmaxf(m, s);
        }
        float sum = 0.f;
        for (int k = 0; k < 4; k++) { l[k] = expf(l[k] - m); sum += l[k]; }
        float inv = 1.f / sum;
        for (int k = 0; k < 4; k++) attn[b * 4 + k] = l[k] * inv;
    }
}

// ---------------- dynamic 3x3 conv + bias + relu ----------------
// Block: 256 thr (tx=lane 0..31, ty 0..7). Tile: 32x32 spatial, 8 co, ci in chunks of 8.
// Per thread: 4 pixels (rows ty, ty+8, ty+16, ty+24) as 2 f32x2 pixel-pairs x 8 co accumulators.
// Weights mixed per-sample from 4-kernel bank into smem as duplicated float2 {w,w}
// so a broadcast LDS.64 feeds fma.rn.f32x2 directly.
template<int CIN>
__global__ void __launch_bounds__(256, 2)
conv_fd_kernel(const float* __restrict__ x, const float* __restrict__ bank,
               const float* __restrict__ attn, const float* __restrict__ bias,
               float* __restrict__ out) {
    __shared__ float  sx[8][34 * 34 + 2];
    __shared__ float2 sw[8][9][8];

    const int tid = threadIdx.x;
    const int tx = tid & 31, ty = tid >> 5;
    const int b   = blockIdx.z;
    const int co0 = blockIdx.y * 8;
    const int y0  = (blockIdx.x >> 2) * 32;
    const int x0  = (blockIdx.x & 3) * 32;

    const float a0 = attn[b * 4 + 0], a1 = attn[b * 4 + 1];
    const float a2 = attn[b * 4 + 2], a3 = attn[b * 4 + 3];
    const int plane = CIN * 9 * CO;

    unsigned long long acc[2][8];
#pragma unroll
    for (int p = 0; p < 2; p++)
#pragma unroll
        for (int c = 0; c < 8; c++) acc[p][c] = 0ULL;

    const float* xb = x + (size_t)b * CIN * HW * HW;

    for (int ci0 = 0; ci0 < CIN; ci0 += 8) {
        __syncthreads();
        // stage x halo tile (34x34 per ci plane), zero-padded at image borders
        for (int i = tid; i < 8 * 34 * 34; i += 256) {
            int ci = i / (34 * 34);
            int r  = i - ci * (34 * 34);
            int ly = r / 34, lx = r - ly * 34;
            int gy = y0 - 1 + ly, gx = x0 - 1 + lx;
            float v = 0.f;
            if ((unsigned)gy < 128u && (unsigned)gx < 128u)
                v = xb[((ci0 + ci) * HW + gy) * HW + gx];
            sx[ci][r] = v;
        }
        // mix per-sample weights: wd = sum_k attn[k] * bank[k]
        for (int i = tid; i < 8 * 9 * 8; i += 256) {
            int ci  = i / 72;
            int r   = i - ci * 72;
            int tap = r >> 3;
            int col = r & 7;
            int base = ((ci0 + ci) * 9 + tap) * CO + co0 + col;
            float v = a0 * bank[base] + a1 * bank[base + plane]
                    + a2 * bank[base + 2 * plane] + a3 * bank[base + 3 * plane];
            sw[ci][tap][col] = make_float2(v, v);
        }
        __syncthreads();

#pragma unroll 2
        for (int ci = 0; ci < 8; ci++) {
            const float* sp = sx[ci];
#pragma unroll
            for (int p2 = 0; p2 < 2; p2++) {
                const int rA = ty + 16 * p2;   // pixel pair rows rA, rA+8
                const int rB = rA + 8;
                unsigned long long xq[9];
#pragma unroll
                for (int dy = 0; dy < 3; dy++)
#pragma unroll
                    for (int dx = 0; dx < 3; dx++) {
                        float va = sp[(rA + dy) * 34 + tx + dx];
                        float vb = sp[(rB + dy) * 34 + tx + dx];
                        asm("mov.b64 %0, {%1, %2};" : "=l"(xq[dy * 3 + dx]) : "f"(va), "f"(vb));
                    }
#pragma unroll
                for (int t = 0; t < 9; t++) {
                    const unsigned long long* wrow =
                        reinterpret_cast<const unsigned long long*>(&sw[ci][t][0]);
#pragma unroll
                    for (int c = 0; c < 8; c++) {
                        unsigned long long w2 = wrow[c];   // broadcast LDS.64 {w,w}
                        asm("fma.rn.f32x2 %0, %1, %2, %0;"
                            : "+l"(acc[p2][c]) : "l"(w2), "l"(xq[t]));
                    }
                }
            }
        }
    }

    // epilogue: bias + relu + store
#pragma unroll
    for (int c = 0; c < 8; c++) {
        float bv = bias[co0 + c];
        float* ob = out + (size_t)(b * CO + co0 + c) * HW * HW;
#pragma unroll
        for (int p2 = 0; p2 < 2; p2++) {
            float va, vb;
            asm("mov.b64 {%0, %1}, %2;" : "=f"(va), "=f"(vb) : "l"(acc[p2][c]));
            int oyA = y0 + ty + 16 * p2;
            va = fmaxf(va + bv, 0.f);
            vb = fmaxf(vb + bv, 0.f);
            ob[oyA * HW + x0 + tx]       = va;
            ob[(oyA + 8) * HW + x0 + tx] = vb;
        }
    }
}

// ---------------- launch ----------------
extern "C" void kernel_launch(void* const* d_in, const int* in_sizes, int n_in,
                              void* d_out, int out_size) {
    const float* x    = (const float*)d_in[0];
    const float* w1fr = (const float*)d_in[1];
    const float* w1fi = (const float*)d_in[2];
    const float* b1   = (const float*)d_in[3];
    const float* a1w1 = (const float*)d_in[4];
    const float* a1b1 = (const float*)d_in[5];
    const float* a1w2 = (const float*)d_in[6];
    const float* a1b2 = (const float*)d_in[7];
    const float* w2fr = (const float*)d_in[8];
    const float* w2fi = (const float*)d_in[9];
    const float* b2   = (const float*)d_in[10];
    const float* a2w1 = (const float*)d_in[11];
    const float* a2b1 = (const float*)d_in[12];
    const float* a2w2 = (const float*)d_in[13];
    const float* a2b2 = (const float*)d_in[14];
    float* out = (float*)d_out;

    float *yb, *bank1, *bank2, *gapb, *attnb;
    cudaGetSymbolAddress((void**)&yb,    g_y);
    cudaGetSymbolAddress((void**)&bank1, g_bank1);
    cudaGetSymbolAddress((void**)&bank2, g_bank2);
    cudaGetSymbolAddress((void**)&gapb,  g_gap);
    cudaGetSymbolAddress((void**)&attnb, g_attn);

    // synthesize spatial kernel banks (data-independent of x, cheap)
    synth_kernel<<<(4 * CO * 128 + 255) / 256, 256>>>(w1fr, w1fi, bank1, 128);
    synth_kernel<<<(4 * CO * 256 + 255) / 256, 256>>>(w2fr, w2fi, bank2, 256);

    // layer 1
    gap_kernel<<<NB * 128, 256>>>(x, gapb);
    attn_kernel<<<NB, 64>>>(gapb, a1w1, a1b1, a1w2, a1b2, attnb, 128, 32);
    conv_fd_kernel<128><<<dim3(16, CO / 8, NB), 256>>>(x, bank1, attnb, b1, yb);

    // layer 2
    gap_kernel<<<NB * 256, 256>>>(yb, gapb);
    attn_kernel<<<NB, 64>>>(gapb, a2w1, a2b1, a2w2, a2b2, attnb, 256, 64);
    conv_fd_kernel<256><<<dim3(16, CO / 8, NB), 256>>>(yb, bank2, attnb, b2, out);
}

// round 3
// speedup vs baseline: 1.0014x; 1.0014x over previous
#include <cuda_runtime.h>
#include <math.h>

#define CO   256
#define HW   128
#define NB   16

// ---------------- device scratch (no allocations allowed) ----------------
__device__ float g_y[(size_t)NB * CO * HW * HW];        // 268 MB intermediate
__device__ float g_bank1[4 * 128 * 9 * CO];             // [k][ci][tap][co]
__device__ float g_bank2[4 * 256 * 9 * CO];
__device__ float g_gap[NB * 256];
__device__ float g_attn[NB * 4];

// ---------------- irfft2 synthesis: 12 reals -> 9 spatial taps ----------------
// jnp.fft.irfft2(Fr + i Fi, s=(3,3)):
//   G[y,kx]  = sum_ky F[ky,kx] * e^{+2*pi*i*ky*y/3}          (ifft along -2, 1/3 folded later)
//   w[y,x]   = (Re G[y,0] + 2*(Re G[y,1]*cos(2pi x/3) - Im G[y,1]*sin(2pi x/3))) / 9
// (c2r drops Im of bin 0.)
__global__ void synth_kernel(const float* __restrict__ fr, const float* __restrict__ fi,
                             float* __restrict__ bank, int Ci) {
    int idx = blockIdx.x * blockDim.x + threadIdx.x;
    int total = 4 * CO * Ci;
    if (idx >= total) return;
    int ci = idx % Ci;
    int t  = idx / Ci;
    int co = t % CO;
    int k  = t / CO;

    const float* pr = fr + (size_t)idx * 6;   // layout [K][Co][Ci][3][2] contiguous
    const float* pi = fi + (size_t)idx * 6;
    float Fr[3][2], Fi[3][2];
#pragma unroll
    for (int a = 0; a < 3; a++)
#pragma unroll
        for (int x2 = 0; x2 < 2; x2++) {
            Fr[a][x2] = pr[a * 2 + x2];
            Fi[a][x2] = pi[a * 2 + x2];
        }

    const float Hs = 0.86602540378443864676f;           // sqrt(3)/2
    const float cm[3] = { 1.f, -0.5f, -0.5f };          // cos(2*pi*m/3)
    const float sm[3] = { 0.f,  Hs,   -Hs  };           // sin(2*pi*m/3)

    float* outp = bank + ((size_t)(k * Ci + ci) * 9) * CO + co;

#pragma unroll
    for (int y = 0; y < 3; y++) {
        float Gr0 = 0.f, Gr1 = 0.f, Gi1 = 0.f;
#pragma unroll
        for (int ky = 0; ky < 3; ky++) {
            int m = (ky * y) % 3;
            float c = cm[m], s = sm[m];
            Gr0 += Fr[ky][0] * c - Fi[ky][0] * s;
            Gr1 += Fr[ky][1] * c - Fi[ky][1] * s;
            Gi1 += Fr[ky][1] * s + Fi[ky][1] * c;
        }
#pragma unroll
        for (int xx = 0; xx < 3; xx++) {
            float w = (Gr0 + 2.f * (Gr1 * cm[xx] - Gi1 * sm[xx])) * (1.f / 9.f);
            outp[(y * 3 + xx) * CO] = w;
        }
    }
}

// ---------------- global average pool: one block per (b, c) ----------------
__global__ void gap_kernel(const float* __restrict__ in, float* __restrict__ gap) {
    const float4* p = reinterpret_cast<const float4*>(in + (size_t)blockIdx.x * (HW * HW));
    float s = 0.f;
    for (int i = threadIdx.x; i < HW * HW / 4; i += 256) {
        float4 v = p[i];
        s += (v.x + v.y) + (v.z + v.w);
    }
    __shared__ float red[8];
    for (int o = 16; o; o >>= 1) s += __shfl_down_sync(0xffffffffu, s, o);
    if ((threadIdx.x & 31) == 0) red[threadIdx.x >> 5] = s;
    __syncthreads();
    if (threadIdx.x < 8) {
        s = red[threadIdx.x];
        for (int o = 4; o; o >>= 1) s += __shfl_down_sync(0xffu, s, o);
        if (threadIdx.x == 0) gap[blockIdx.x] = s * (1.f / (HW * HW));
    }
}

// ---------------- GAP -> MLP -> softmax attention, one block per sample ----------------
__global__ void attn_kernel(const float* __restrict__ gap, const float* __restrict__ w1,
                            const float* __restrict__ b1, const float* __restrict__ w2,
                            const float* __restrict__ b2, float* __restrict__ attn,
                            int C, int Hd) {
    __shared__ float gs[256];
    __shared__ float hbuf[64];
    int b = blockIdx.x;
    for (int i = threadIdx.x; i < C; i += blockDim.x) gs[i] = gap[b * C + i];
    __syncthreads();
    for (int j = threadIdx.x; j < Hd; j += blockDim.x) {
        float s = b1[j];
        for (int c = 0; c < C; c++) s += gs[c] * w1[c * Hd + j];
        hbuf[j] = fmaxf(s, 0.f);
    }
    __syncthreads();
    if (threadIdx.x == 0) {
        float l[4];
        float m = -1e30f;
        for (int k = 0; k < 4; k++) {
            float s = b2[k];
            for (int j = 0; j < Hd; j++) s += hbuf[j] * w2[j * 4 + k];
            l[k] = s;
            m = fmaxf(m, s);
        }
        float sum = 0.f;
        for (int k = 0; k < 4; k++) { l[k] = expf(l[k] - m); sum += l[k]; }
        float inv = 1.f / sum;
        for (int k = 0; k < 4; k++) attn[b * 4 + k] = l[k] * inv;
    }
}

// ---------------- dynamic 3x3 conv + bias + relu ----------------
// Block: 256 thr (tx=lane 0..31, ty 0..7). Tile: 32x32 spatial, 8 co, ci in chunks of 8.
// Per thread: 4 pixels (rows ty, ty+8, ty+16, ty+24) as 2 f32x2 pixel-pairs x 8 co accumulators.
// Weights mixed per-sample from 4-kernel bank into smem as duplicated float2 {w,w}
// so a broadcast LDS.64 feeds fma.rn.f32x2 directly.
template<int CIN>
__global__ void __launch_bounds__(256, 2)
conv_fd_kernel(const float* __restrict__ x, const float* __restrict__ bank,
               const float* __restrict__ attn, const float* __restrict__ bias,
               float* __restrict__ out) {
    __shared__ float  sx[8][34 * 34 + 2];
    __shared__ float2 sw[8][9][8];

    const int tid = threadIdx.x;
    const int tx = tid & 31, ty = tid >> 5;
    const int b   = blockIdx.z;
    const int co0 = blockIdx.y * 8;
    const int y0  = (blockIdx.x >> 2) * 32;
    const int x0  = (blockIdx.x & 3) * 32;

    const float a0 = attn[b * 4 + 0], a1 = attn[b * 4 + 1];
    const float a2 = attn[b * 4 + 2], a3 = attn[b * 4 + 3];
    const int plane = CIN * 9 * CO;

    unsigned long long acc[2][8];
#pragma unroll
    for (int p = 0; p < 2; p++)
#pragma unroll
        for (int c = 0; c < 8; c++) acc[p][c] = 0ULL;

    const float* xb = x + (size_t)b * CIN * HW * HW;

    for (int ci0 = 0; ci0 < CIN; ci0 += 8) {
        __syncthreads();
        // stage x halo tile (34x34 per ci plane), zero-padded at image borders
        for (int i = tid; i < 8 * 34 * 34; i += 256) {
            int ci = i / (34 * 34);
            int r  = i - ci * (34 * 34);
            int ly = r / 34, lx = r - ly * 34;
            int gy = y0 - 1 + ly, gx = x0 - 1 + lx;
            float v = 0.f;
            if ((unsigned)gy < 128u && (unsigned)gx < 128u)
                v = xb[((ci0 + ci) * HW + gy) * HW + gx];
            sx[ci][r] = v;
        }
        // mix per-sample weights: wd = sum_k attn[k] * bank[k]
        for (int i = tid; i < 8 * 9 * 8; i += 256) {
            int ci  = i / 72;
            int r   = i - ci * 72;
            int tap = r >> 3;
            int col = r & 7;
            int base = ((ci0 + ci) * 9 + tap) * CO + co0 + col;
            float v = a0 * bank[base] + a1 * bank[base + plane]
                    + a2 * bank[base + 2 * plane] + a3 * bank[base + 3 * plane];
            sw[ci][tap][col] = make_float2(v, v);
        }
        __syncthreads();

#pragma unroll 2
        for (int ci = 0; ci < 8; ci++) {
            const float* sp = sx[ci];
#pragma unroll
            for (int p2 = 0; p2 < 2; p2++) {
                const int rA = ty + 16 * p2;   // pixel pair rows rA, rA+8
                const int rB = rA + 8;
                unsigned long long xq[9];
#pragma unroll
                for (int dy = 0; dy < 3; dy++)
#pragma unroll
                    for (int dx = 0; dx < 3; dx++) {
                        float va = sp[(rA + dy) * 34 + tx + dx];
                        float vb = sp[(rB + dy) * 34 + tx + dx];
                        asm("mov.b64 %0, {%1, %2};" : "=l"(xq[dy * 3 + dx]) : "f"(va), "f"(vb));
                    }
#pragma unroll
                for (int t = 0; t < 9; t++) {
                    const unsigned long long* wrow =
                        reinterpret_cast<const unsigned long long*>(&sw[ci][t][0]);
#pragma unroll
                    for (int c = 0; c < 8; c++) {
                        unsigned long long w2 = wrow[c];   // broadcast LDS.64 {w,w}
                        asm("fma.rn.f32x2 %0, %1, %2, %0;"
                            : "+l"(acc[p2][c]) : "l"(w2), "l"(xq[t]));
                    }
                }
            }
        }
    }

    // epilogue: bias + relu + store
#pragma unroll
    for (int c = 0; c < 8; c++) {
        float bv = bias[co0 + c];
        float* ob = out + (size_t)(b * CO + co0 + c) * HW * HW;
#pragma unroll
        for (int p2 = 0; p2 < 2; p2++) {
            float va, vb;
            asm("mov.b64 {%0, %1}, %2;" : "=f"(va), "=f"(vb) : "l"(acc[p2][c]));
            int oyA = y0 + ty + 16 * p2;
            va = fmaxf(va + bv, 0.f);
            vb = fmaxf(vb + bv, 0.f);
            ob[oyA * HW + x0 + tx]       = va;
            ob[(oyA + 8) * HW + x0 + tx] = vb;
        }
    }
}

// ---------------- launch ----------------
extern "C" void kernel_launch(void* const* d_in, const int* in_sizes, int n_in,
                              void* d_out, int out_size) {
    const float* x    = (const float*)d_in[0];
    const float* w1fr = (const float*)d_in[1];
    const float* w1fi = (const float*)d_in[2];
    const float* b1   = (const float*)d_in[3];
    const float* a1w1 = (const float*)d_in[4];
    const float* a1b1 = (const float*)d_in[5];
    const float* a1w2 = (const float*)d_in[6];
    const float* a1b2 = (const float*)d_in[7];
    const float* w2fr = (const float*)d_in[8];
    const float* w2fi = (const float*)d_in[9];
    const float* b2   = (const float*)d_in[10];
    const float* a2w1 = (const float*)d_in[11];
    const float* a2b1 = (const float*)d_in[12];
    const float* a2w2 = (const float*)d_in[13];
    const float* a2b2 = (const float*)d_in[14];
    float* out = (float*)d_out;

    float *yb, *bank1, *bank2, *gapb, *attnb;
    cudaGetSymbolAddress((void**)&yb,    g_y);
    cudaGetSymbolAddress((void**)&bank1, g_bank1);
    cudaGetSymbolAddress((void**)&bank2, g_bank2);
    cudaGetSymbolAddress((void**)&gapb,  g_gap);
    cudaGetSymbolAddress((void**)&attnb, g_attn);

    // synthesize spatial kernel banks (data-independent of x, cheap)
    synth_kernel<<<(4 * CO * 128 + 255) / 256, 256>>>(w1fr, w1fi, bank1, 128);
    synth_kernel<<<(4 * CO * 256 + 255) / 256, 256>>>(w2fr, w2fi, bank2, 256);

    // layer 1
    gap_kernel<<<NB * 128, 256>>>(x, gapb);
    attn_kernel<<<NB, 64>>>(gapb, a1w1, a1b1, a1w2, a1b2, attnb, 128, 32);
    conv_fd_kernel<128><<<dim3(16, CO / 8, NB), 256>>>(x, bank1, attnb, b1, yb);

    // layer 2
    gap_kernel<<<NB * 256, 256>>>(yb, gapb);
    attn_kernel<<<NB, 64>>>(gapb, a2w1, a2b1, a2w2, a2b2, attnb, 256, 64);
    conv_fd_kernel<256><<<dim3(16, CO / 8, NB), 256>>>(yb, bank2, attnb, b2, out);
}